// round 1
// baseline (speedup 1.0000x reference)
#include <cuda_runtime.h>

#define BSZ   640
#define INCH  2048
#define OUTCH 696
#define NS    174
#define CHROWS 320   // ghost-BN chunk rows (BS/2)

// ---------------- scratch (device globals; no allocation allowed) ----------------
__device__ float g_h   [BSZ * OUTCH];   // raw GEMM output
__device__ float g_hmul[BSZ * OUTCH];   // prior * BN(h)
__device__ float g_q   [OUTCH * BSZ];   // transposed [c][l], pre-scaled by log2(e)
__device__ float g_k   [OUTCH * BSZ];
__device__ float g_v   [OUTCH * BSZ];
__device__ float g_o   [OUTCH * BSZ];
__device__ float g_sum [2 * OUTCH];
__device__ float g_sq  [2 * OUTCH];

__device__ __forceinline__ float ex2(float x) {
    float y;
    asm("ex2.approx.ftz.f32 %0, %1;" : "=f"(y) : "f"(x));
    return y;
}

#define LOG2E 1.4426950408889634f

// ---------------- kernel 0: zero BN stat accumulators ----------------
__global__ void zero_stats_kernel() {
    int i = blockIdx.x * blockDim.x + threadIdx.x;
    if (i < 2 * OUTCH) { g_sum[i] = 0.f; g_sq[i] = 0.f; }
}

// ---------------- kernel 1: fp32 GEMM h = x @ w^T, fused BN chunk stats ----------------
// 64x64 tile, BK=16, 256 threads, each thread 4x4 outputs.
__global__ __launch_bounds__(256) void gemm_kernel(const float* __restrict__ x,
                                                   const float* __restrict__ w) {
    __shared__ float As[16][64];
    __shared__ float Bs[16][64];
    __shared__ float red[64][16];

    const int bm = blockIdx.y * 64;
    const int bn = blockIdx.x * 64;
    const int tid = threadIdx.x;
    const int tx = tid & 15, ty = tid >> 4;
    const int lr = tid >> 2, lc = (tid & 3) * 4;

    float acc[4][4];
    #pragma unroll
    for (int i = 0; i < 4; i++)
        #pragma unroll
        for (int j = 0; j < 4; j++) acc[i][j] = 0.f;

    const float* ax = x + (bm + lr) * INCH + lc;
    const float* aw = w + (bn + lr) * INCH + lc;
    const bool wvalid = (bn + lr) < OUTCH;

    for (int k0 = 0; k0 < INCH; k0 += 16) {
        float4 a = *(const float4*)(ax + k0);
        float4 b = wvalid ? *(const float4*)(aw + k0) : make_float4(0.f, 0.f, 0.f, 0.f);
        As[lc + 0][lr] = a.x; As[lc + 1][lr] = a.y; As[lc + 2][lr] = a.z; As[lc + 3][lr] = a.w;
        Bs[lc + 0][lr] = b.x; Bs[lc + 1][lr] = b.y; Bs[lc + 2][lr] = b.z; Bs[lc + 3][lr] = b.w;
        __syncthreads();
        #pragma unroll
        for (int k = 0; k < 16; k++) {
            float4 av = *(const float4*)&As[k][ty * 4];
            float4 bv = *(const float4*)&Bs[k][tx * 4];
            float ar[4] = {av.x, av.y, av.z, av.w};
            float br[4] = {bv.x, bv.y, bv.z, bv.w};
            #pragma unroll
            for (int i = 0; i < 4; i++)
                #pragma unroll
                for (int j = 0; j < 4; j++)
                    acc[i][j] = fmaf(ar[i], br[j], acc[i][j]);
        }
        __syncthreads();
    }

    // store h
    #pragma unroll
    for (int i = 0; i < 4; i++) {
        int row = bm + ty * 4 + i;
        #pragma unroll
        for (int j = 0; j < 4; j++) {
            int col = bn + tx * 4 + j;
            if (col < OUTCH) g_h[row * OUTCH + col] = acc[i][j];
        }
    }

    // fused BN chunk stats: per-column sum & sumsq over this tile's 64 rows.
    // 64-row tiles never straddle the 320-row chunk boundary.
    const int chunk = bm / CHROWS;
    float cs[4], cq[4];
    #pragma unroll
    for (int j = 0; j < 4; j++) {
        cs[j] = acc[0][j] + acc[1][j] + acc[2][j] + acc[3][j];
        cq[j] = acc[0][j] * acc[0][j] + acc[1][j] * acc[1][j]
              + acc[2][j] * acc[2][j] + acc[3][j] * acc[3][j];
    }
    #pragma unroll
    for (int j = 0; j < 4; j++) red[tx * 4 + j][ty] = cs[j];
    __syncthreads();
    if (tid < 64) {
        float s = 0.f;
        #pragma unroll
        for (int t = 0; t < 16; t++) s += red[tid][t];
        if (bn + tid < OUTCH) atomicAdd(&g_sum[chunk * OUTCH + bn + tid], s);
    }
    __syncthreads();
    #pragma unroll
    for (int j = 0; j < 4; j++) red[tx * 4 + j][ty] = cq[j];
    __syncthreads();
    if (tid < 64) {
        float s = 0.f;
        #pragma unroll
        for (int t = 0; t < 16; t++) s += red[tid][t];
        if (bn + tid < OUTCH) atomicAdd(&g_sq[chunk * OUTCH + bn + tid], s);
    }
}

// ---------------- kernel 2: BN finalize + prior-mul + q/k/v projections ----------------
// one thread per (l, n); writes hmul [l][c] and q/k/v transposed [c][l].
__global__ __launch_bounds__(256) void bn_qkv_kernel(const float* __restrict__ prior,
                                                     const float* __restrict__ gamma,
                                                     const float* __restrict__ beta,
                                                     const float* __restrict__ ipw,
                                                     const float* __restrict__ ipb) {
    int id = blockIdx.x * blockDim.x + threadIdx.x;
    if (id >= BSZ * NS) return;
    int l = id / NS, n = id % NS;
    int c0 = n * 4;
    int chunk = l / CHROWS;

    float4 hr = *(const float4*)(g_h + l * OUTCH + c0);
    float4 pr = *(const float4*)(prior + l * OUTCH + c0);
    float hv[4] = {hr.x, hr.y, hr.z, hr.w};
    float pv[4] = {pr.x, pr.y, pr.z, pr.w};
    float hm[4];
    #pragma unroll
    for (int e = 0; e < 4; e++) {
        int c = c0 + e;
        float mean = g_sum[chunk * OUTCH + c] * (1.f / CHROWS);
        float var  = g_sq [chunk * OUTCH + c] * (1.f / CHROWS) - mean * mean;
        float hb = (hv[e] - mean) * rsqrtf(var + 1e-5f) * gamma[c] + beta[c];
        hm[e] = pv[e] * hb;
    }
    *(float4*)(g_hmul + l * OUTCH + c0) = make_float4(hm[0], hm[1], hm[2], hm[3]);

    #pragma unroll
    for (int e = 0; e < 4; e++) {
        float q = ipb[e], k = ipb[4 + e], v = ipb[8 + e];
        #pragma unroll
        for (int e2 = 0; e2 < 4; e2++) {
            q = fmaf(ipw[e * 4 + e2],       hm[e2], q);
            k = fmaf(ipw[(4 + e) * 4 + e2], pv[e2], k);
            v = fmaf(ipw[(8 + e) * 4 + e2], pv[e2], v);
        }
        g_q[(c0 + e) * BSZ + l] = q * LOG2E;   // fold log2(e) for single-MUFU exp
        g_k[(c0 + e) * BSZ + l] = k;
        g_v[(c0 + e) * BSZ + l] = v;
    }
}

// ---------------- kernel 3: per-channel scalar attention ----------------
// one block per channel c (696 blocks), 640 threads (one per query l).
__global__ __launch_bounds__(640) void attn_kernel() {
    __shared__ float ks[BSZ];
    __shared__ float vs[BSZ];
    const int c = blockIdx.x, t = threadIdx.x;
    ks[t] = g_k[c * BSZ + t];
    vs[t] = g_v[c * BSZ + t];
    __syncthreads();

    const float ql = g_q[c * BSZ + t];   // already q*log2e
    float d = 0.f, nv = 0.f;
    const float4* k4 = (const float4*)ks;
    const float4* v4 = (const float4*)vs;
    #pragma unroll 4
    for (int s = 0; s < BSZ / 4; s++) {
        float4 kk = k4[s], vv = v4[s];
        float e0 = ex2(ql * kk.x);
        float e1 = ex2(ql * kk.y);
        float e2 = ex2(ql * kk.z);
        float e3 = ex2(ql * kk.w);
        d += (e0 + e1) + (e2 + e3);
        nv = fmaf(e0, vv.x, fmaf(e1, vv.y, fmaf(e2, vv.z, fmaf(e3, vv.w, nv))));
    }
    g_o[c * BSZ + t] = nv / d;
}

// ---------------- kernel 4: out_proj + residual + row softmax ----------------
__global__ __launch_bounds__(256) void epi_kernel(const float* __restrict__ opw,
                                                  const float* __restrict__ opb,
                                                  float* __restrict__ out) {
    __shared__ float orow[OUTCH];
    __shared__ float sh[OUTCH];
    __shared__ float rbuf[8];
    const int l = blockIdx.x, tid = threadIdx.x;

    for (int c = tid; c < OUTCH; c += 256) orow[c] = g_o[c * BSZ + l];
    __syncthreads();

    float lmax = -1e30f;
    for (int c = tid; c < OUTCH; c += 256) {
        int n = c >> 2, e = c & 3;
        float y = opb[e];
        #pragma unroll
        for (int e2 = 0; e2 < 4; e2++) y = fmaf(opw[e * 4 + e2], orow[n * 4 + e2], y);
        float lg = g_hmul[l * OUTCH + c] + y;
        sh[c] = lg;
        lmax = fmaxf(lmax, lg);
    }
    #pragma unroll
    for (int o = 16; o; o >>= 1) lmax = fmaxf(lmax, __shfl_xor_sync(0xFFFFFFFFu, lmax, o));
    if ((tid & 31) == 0) rbuf[tid >> 5] = lmax;
    __syncthreads();
    float bmax = rbuf[0];
    #pragma unroll
    for (int i = 1; i < 8; i++) bmax = fmaxf(bmax, rbuf[i]);
    __syncthreads();   // all reads of rbuf done before reuse

    float sum = 0.f;
    for (int c = tid; c < OUTCH; c += 256) {
        float e = ex2((sh[c] - bmax) * LOG2E);
        sh[c] = e;
        sum += e;
    }
    #pragma unroll
    for (int o = 16; o; o >>= 1) sum += __shfl_xor_sync(0xFFFFFFFFu, sum, o);
    if ((tid & 31) == 0) rbuf[tid >> 5] = sum;
    __syncthreads();
    float bsum = 0.f;
    #pragma unroll
    for (int i = 0; i < 8; i++) bsum += rbuf[i];
    float inv = 1.f / bsum;
    for (int c = tid; c < OUTCH; c += 256) out[l * OUTCH + c] = sh[c] * inv;
}

// ---------------- launch ----------------
extern "C" void kernel_launch(void* const* d_in, const int* in_sizes, int n_in,
                              void* d_out, int out_size) {
    const float* x     = (const float*)d_in[0];
    const float* prior = (const float*)d_in[1];
    const float* w_lin = (const float*)d_in[2];
    const float* gamma = (const float*)d_in[3];
    const float* beta  = (const float*)d_in[4];
    const float* ipw   = (const float*)d_in[5];
    const float* ipb   = (const float*)d_in[6];
    const float* opw   = (const float*)d_in[7];
    const float* opb   = (const float*)d_in[8];
    float* out = (float*)d_out;

    zero_stats_kernel<<<(2 * OUTCH + 255) / 256, 256>>>();
    dim3 ggrid((OUTCH + 63) / 64, BSZ / 64);   // 11 x 10
    gemm_kernel<<<ggrid, 256>>>(x, w_lin);
    bn_qkv_kernel<<<(BSZ * NS + 255) / 256, 256>>>(prior, gamma, beta, ipw, ipb);
    attn_kernel<<<OUTCH, BSZ>>>();
    epi_kernel<<<BSZ, 256>>>(opw, opb, out);
}

// round 2
// speedup vs baseline: 1.4376x; 1.4376x over previous
#include <cuda_runtime.h>

#define BSZ   640
#define INCH  2048
#define OUTCH 696
#define NS    174
#define CHROWS 320   // ghost-BN chunk rows
#define KSPLIT 4
#define KS    (INCH / KSPLIT)   // 512

// ---------------- scratch ----------------
__device__ float g_hpart[KSPLIT][BSZ * OUTCH]; // split-K partial GEMM outputs
__device__ float g_h   [BSZ * OUTCH];
__device__ float g_hmul[BSZ * OUTCH];
__device__ float g_q   [OUTCH * BSZ];   // [c][l], pre-scaled by log2(e)
__device__ float g_k   [OUTCH * BSZ];
__device__ float g_v   [OUTCH * BSZ];
__device__ float g_o   [OUTCH * BSZ];
__device__ float g_sum [2 * OUTCH];
__device__ float g_sq  [2 * OUTCH];

__device__ __forceinline__ float ex2(float x) {
    float y;
    asm("ex2.approx.ftz.f32 %0, %1;" : "=f"(y) : "f"(x));
    return y;
}
#define LOG2E 1.4426950408889634f

// ---------------- kernel 1: split-K GEMM, 64x64 tile, 128 thr, 8x4/thread ----------------
__global__ __launch_bounds__(128) void gemm_kernel(const float* __restrict__ x,
                                                   const float* __restrict__ w) {
    __shared__ float As[16][68];
    __shared__ float Bs[16][68];

    const int bm = blockIdx.y * 64;
    const int bn = blockIdx.x * 64;
    const int slice = blockIdx.z;
    const int tid = threadIdx.x;
    const int tx = tid & 15, ty = tid >> 4;      // compute map: rows ty*8.., cols tx*4..
    const int lkq = tid & 3, lrow = tid >> 2;    // loader map: k-quad, row 0..31

    float acc[8][4];
    #pragma unroll
    for (int i = 0; i < 8; i++)
        #pragma unroll
        for (int j = 0; j < 4; j++) acc[i][j] = 0.f;

    const float* ax = x + (size_t)(bm + lrow) * INCH + slice * KS + lkq * 4;
    const float* aw = w + (size_t)(bn + lrow) * INCH + slice * KS + lkq * 4;
    const bool wv0 = (bn + lrow)      < OUTCH;
    const bool wv1 = (bn + lrow + 32) < OUTCH;
    const float4 z4 = make_float4(0.f, 0.f, 0.f, 0.f);

    float4 a0 = *(const float4*)(ax);
    float4 a1 = *(const float4*)(ax + 32 * INCH);
    float4 b0 = wv0 ? *(const float4*)(aw) : z4;
    float4 b1 = wv1 ? *(const float4*)(aw + 32 * INCH) : z4;

    for (int k0 = 0; k0 < KS; k0 += 16) {
        __syncthreads();
        As[lkq * 4 + 0][lrow] = a0.x; As[lkq * 4 + 1][lrow] = a0.y;
        As[lkq * 4 + 2][lrow] = a0.z; As[lkq * 4 + 3][lrow] = a0.w;
        As[lkq * 4 + 0][lrow + 32] = a1.x; As[lkq * 4 + 1][lrow + 32] = a1.y;
        As[lkq * 4 + 2][lrow + 32] = a1.z; As[lkq * 4 + 3][lrow + 32] = a1.w;
        Bs[lkq * 4 + 0][lrow] = b0.x; Bs[lkq * 4 + 1][lrow] = b0.y;
        Bs[lkq * 4 + 2][lrow] = b0.z; Bs[lkq * 4 + 3][lrow] = b0.w;
        Bs[lkq * 4 + 0][lrow + 32] = b1.x; Bs[lkq * 4 + 1][lrow + 32] = b1.y;
        Bs[lkq * 4 + 2][lrow + 32] = b1.z; Bs[lkq * 4 + 3][lrow + 32] = b1.w;
        __syncthreads();

        if (k0 + 16 < KS) {   // prefetch next tile; overlaps compute
            a0 = *(const float4*)(ax + k0 + 16);
            a1 = *(const float4*)(ax + 32 * INCH + k0 + 16);
            b0 = wv0 ? *(const float4*)(aw + k0 + 16) : z4;
            b1 = wv1 ? *(const float4*)(aw + 32 * INCH + k0 + 16) : z4;
        }

        #pragma unroll
        for (int k = 0; k < 16; k++) {
            float4 alo = *(const float4*)&As[k][ty * 8];
            float4 ahi = *(const float4*)&As[k][ty * 8 + 4];
            float4 bv  = *(const float4*)&Bs[k][tx * 4];
            float ar[8] = {alo.x, alo.y, alo.z, alo.w, ahi.x, ahi.y, ahi.z, ahi.w};
            float br[4] = {bv.x, bv.y, bv.z, bv.w};
            #pragma unroll
            for (int i = 0; i < 8; i++)
                #pragma unroll
                for (int j = 0; j < 4; j++)
                    acc[i][j] = fmaf(ar[i], br[j], acc[i][j]);
        }
    }

    float* dst = g_hpart[slice];
    const int col = bn + tx * 4;
    if (col < OUTCH) {
        #pragma unroll
        for (int i = 0; i < 8; i++) {
            int row = bm + ty * 8 + i;
            *(float4*)(dst + (size_t)row * OUTCH + col) =
                make_float4(acc[i][0], acc[i][1], acc[i][2], acc[i][3]);
        }
    }
}

// ---------------- kernel 2: reduce split-K parts -> g_h, ghost-BN chunk stats ----------------
__global__ __launch_bounds__(256) void reduce_stats_kernel() {
    __shared__ float ssum[8][32];
    __shared__ float ssq [8][32];
    const int c = threadIdx.x & 31, g = threadIdx.x >> 5;
    const int cg = blockIdx.x * 32 + c;
    const int chunk = blockIdx.y;
    const bool valid = cg < OUTCH;

    float s = 0.f, sq = 0.f;
    if (valid) {
        #pragma unroll 4
        for (int r = 0; r < 40; r++) {
            int row = chunk * CHROWS + g * 40 + r;
            size_t idx = (size_t)row * OUTCH + cg;
            float h = g_hpart[0][idx] + g_hpart[1][idx] + g_hpart[2][idx] + g_hpart[3][idx];
            g_h[idx] = h;
            s += h; sq += h * h;
        }
    }
    ssum[g][c] = s; ssq[g][c] = sq;
    __syncthreads();
    if (g == 0 && valid) {
        float ts = 0.f, tq = 0.f;
        #pragma unroll
        for (int i = 0; i < 8; i++) { ts += ssum[i][c]; tq += ssq[i][c]; }
        g_sum[chunk * OUTCH + cg] = ts;
        g_sq [chunk * OUTCH + cg] = tq;
    }
}

// ---------------- kernel 3: BN finalize + prior-mul + q/k/v (coalesced transpose) ----------------
// block: 256 thr = 8 n-groups x 32 l; tile c-range 32, l-range 32.
__global__ __launch_bounds__(256) void bn_qkv_kernel(const float* __restrict__ prior,
                                                     const float* __restrict__ gamma,
                                                     const float* __restrict__ beta,
                                                     const float* __restrict__ ipw,
                                                     const float* __restrict__ ipb) {
    __shared__ float qs[32][33];
    __shared__ float ks[32][33];
    __shared__ float vs[32][33];

    const int tid = threadIdx.x;
    const int ni = tid & 7, li = tid >> 3;
    const int nb = blockIdx.x, lb = blockIdx.y;
    const int n = nb * 8 + ni;
    const int l = lb * 32 + li;

    if (n < NS) {
        const int c0 = n * 4;
        const int chunk = l / CHROWS;
        float4 hr = *(const float4*)(g_h + (size_t)l * OUTCH + c0);
        float4 pr = *(const float4*)(prior + (size_t)l * OUTCH + c0);
        float hv[4] = {hr.x, hr.y, hr.z, hr.w};
        float pv[4] = {pr.x, pr.y, pr.z, pr.w};
        float hm[4];
        #pragma unroll
        for (int e = 0; e < 4; e++) {
            int cc = c0 + e;
            float mean = g_sum[chunk * OUTCH + cc] * (1.f / CHROWS);
            float var  = g_sq [chunk * OUTCH + cc] * (1.f / CHROWS) - mean * mean;
            float hb = (hv[e] - mean) * rsqrtf(var + 1e-5f) * gamma[cc] + beta[cc];
            hm[e] = pv[e] * hb;
        }
        *(float4*)(g_hmul + (size_t)l * OUTCH + c0) = make_float4(hm[0], hm[1], hm[2], hm[3]);

        #pragma unroll
        for (int e = 0; e < 4; e++) {
            float q = ipb[e], k = ipb[4 + e], v = ipb[8 + e];
            #pragma unroll
            for (int e2 = 0; e2 < 4; e2++) {
                q = fmaf(ipw[e * 4 + e2],       hm[e2], q);
                k = fmaf(ipw[(4 + e) * 4 + e2], pv[e2], k);
                v = fmaf(ipw[(8 + e) * 4 + e2], pv[e2], v);
            }
            qs[ni * 4 + e][li] = q * LOG2E;
            ks[ni * 4 + e][li] = k;
            vs[ni * 4 + e][li] = v;
        }
    }
    __syncthreads();

    // transposed coalesced writes: 128B runs along l
    const int lo = tid & 31;
    #pragma unroll
    for (int p = 0; p < 4; p++) {
        int cl = (tid >> 5) + p * 8;
        int cc = nb * 32 + cl;
        if (cc < OUTCH) {
            size_t o = (size_t)cc * BSZ + lb * 32 + lo;
            g_q[o] = qs[cl][lo];
            g_k[o] = ks[cl][lo];
            g_v[o] = vs[cl][lo];
        }
    }
}

// ---------------- kernel 4: per-channel scalar attention ----------------
__global__ __launch_bounds__(640) void attn_kernel() {
    __shared__ float kk_s[BSZ];
    __shared__ float vv_s[BSZ];
    const int c = blockIdx.x, t = threadIdx.x;
    kk_s[t] = g_k[(size_t)c * BSZ + t];
    vv_s[t] = g_v[(size_t)c * BSZ + t];
    __syncthreads();

    const float ql = g_q[(size_t)c * BSZ + t];
    float d = 0.f, nv = 0.f;
    const float4* k4 = (const float4*)kk_s;
    const float4* v4 = (const float4*)vv_s;
    #pragma unroll 4
    for (int s = 0; s < BSZ / 4; s++) {
        float4 kv = k4[s], vv = v4[s];
        float e0 = ex2(ql * kv.x);
        float e1 = ex2(ql * kv.y);
        float e2 = ex2(ql * kv.z);
        float e3 = ex2(ql * kv.w);
        d += (e0 + e1) + (e2 + e3);
        nv = fmaf(e0, vv.x, fmaf(e1, vv.y, fmaf(e2, vv.z, fmaf(e3, vv.w, nv))));
    }
    g_o[(size_t)c * BSZ + t] = nv / d;
}

// ---------------- kernel 5: out_proj + residual + row softmax ----------------
__global__ __launch_bounds__(256) void epi_kernel(const float* __restrict__ opw,
                                                  const float* __restrict__ opb,
                                                  float* __restrict__ out) {
    __shared__ float orow[OUTCH];
    __shared__ float sh[OUTCH];
    __shared__ float rbuf[8];
    const int l = blockIdx.x, tid = threadIdx.x;

    for (int c = tid; c < OUTCH; c += 256) orow[c] = g_o[(size_t)c * BSZ + l];
    __syncthreads();

    float lmax = -1e30f;
    for (int c = tid; c < OUTCH; c += 256) {
        int n = c >> 2, e = c & 3;
        float y = opb[e];
        #pragma unroll
        for (int e2 = 0; e2 < 4; e2++) y = fmaf(opw[e * 4 + e2], orow[n * 4 + e2], y);
        float lg = g_hmul[(size_t)l * OUTCH + c] + y;
        sh[c] = lg;
        lmax = fmaxf(lmax, lg);
    }
    #pragma unroll
    for (int o = 16; o; o >>= 1) lmax = fmaxf(lmax, __shfl_xor_sync(0xFFFFFFFFu, lmax, o));
    if ((tid & 31) == 0) rbuf[tid >> 5] = lmax;
    __syncthreads();
    float bmax = rbuf[0];
    #pragma unroll
    for (int i = 1; i < 8; i++) bmax = fmaxf(bmax, rbuf[i]);
    __syncthreads();

    float sum = 0.f;
    for (int c = tid; c < OUTCH; c += 256) {
        float e = ex2((sh[c] - bmax) * LOG2E);
        sh[c] = e;
        sum += e;
    }
    #pragma unroll
    for (int o = 16; o; o >>= 1) sum += __shfl_xor_sync(0xFFFFFFFFu, sum, o);
    if ((tid & 31) == 0) rbuf[tid >> 5] = sum;
    __syncthreads();
    float bsum = 0.f;
    #pragma unroll
    for (int i = 0; i < 8; i++) bsum += rbuf[i];
    float inv = 1.f / bsum;
    for (int c = tid; c < OUTCH; c += 256) out[(size_t)l * OUTCH + c] = sh[c] * inv;
}

// ---------------- launch ----------------
extern "C" void kernel_launch(void* const* d_in, const int* in_sizes, int n_in,
                              void* d_out, int out_size) {
    const float* x     = (const float*)d_in[0];
    const float* prior = (const float*)d_in[1];
    const float* w_lin = (const float*)d_in[2];
    const float* gamma = (const float*)d_in[3];
    const float* beta  = (const float*)d_in[4];
    const float* ipw   = (const float*)d_in[5];
    const float* ipb   = (const float*)d_in[6];
    const float* opw   = (const float*)d_in[7];
    const float* opb   = (const float*)d_in[8];
    float* out = (float*)d_out;

    dim3 ggrid((OUTCH + 63) / 64, BSZ / 64, KSPLIT);   // 11 x 10 x 4 = 440 CTAs
    gemm_kernel<<<ggrid, 128>>>(x, w_lin);
    reduce_stats_kernel<<<dim3((OUTCH + 31) / 32, 2), 256>>>();
    bn_qkv_kernel<<<dim3((NS + 7) / 8, BSZ / 32), 256>>>(prior, gamma, beta, ipw, ipb);
    attn_kernel<<<OUTCH, BSZ>>>();
    epi_kernel<<<BSZ, 256>>>(opw, opb, out);
}